// round 1
// baseline (speedup 1.0000x reference)
#include <cuda_runtime.h>

#define Bsz 8192
#define Lsz 16
#define Hsz 512
#define Ssz 64
#define Dsz 16

// Scratch (static device globals: allowed; no runtime allocation)
__device__ float g_buf0[Bsz * Hsz];
__device__ float g_buf1[Bsz * Hsz];
__device__ int g_perm[Bsz];
__device__ int g_dstart[Dsz + 1];
__device__ int g_dcount[Dsz];
__device__ int g_dfill[Dsz];

__device__ __forceinline__ float lrelu(float x) { return x >= 0.0f ? x : 0.2f * x; }

// ---------------- domain bucketing ----------------
__global__ void k_zero() {
    int t = threadIdx.x;
    if (t < Dsz) g_dcount[t] = 0;
}

__global__ void k_hist(const int* __restrict__ y) {
    int i = blockIdx.x * blockDim.x + threadIdx.x;
    if (i < Bsz) atomicAdd(&g_dcount[y[i]], 1);
}

__global__ void k_prefix() {
    int s = 0;
    for (int d = 0; d < Dsz; ++d) {
        g_dstart[d] = s;
        g_dfill[d] = s;
        s += g_dcount[d];
    }
    g_dstart[Dsz] = s;
}

__global__ void k_scatter(const int* __restrict__ y) {
    int i = blockIdx.x * blockDim.x + threadIdx.x;
    if (i < Bsz) {
        int p = atomicAdd(&g_dfill[y[i]], 1);
        g_perm[p] = i;
    }
}

// ---------------- layer 0: z[perm[p]] @ tW0 + tb0, lrelu -> g_buf0 ----------------
// grid = Bsz/32 blocks of 256 threads; each block: 32 packed rows x 512 cols
__global__ __launch_bounds__(256) void k_layer0(const float* __restrict__ z,
                                                const float* __restrict__ W,
                                                const float* __restrict__ bias) {
    __shared__ float sW[Lsz * Hsz];
    __shared__ float sb[Hsz];
    int tid = threadIdx.x;
    for (int i = tid; i < Lsz * Hsz; i += 256) sW[i] = W[i];
    for (int i = tid; i < Hsz; i += 256) sb[i] = bias[i];
    __syncthreads();

    int w = tid >> 5, lane = tid & 31;
    for (int q = 0; q < 4; ++q) {
        int p = blockIdx.x * 32 + w * 4 + q;
        int b = g_perm[p];
        float zr[Lsz];
#pragma unroll
        for (int k = 0; k < Lsz; ++k) zr[k] = __ldg(&z[b * Lsz + k]);
        for (int c = lane; c < Hsz; c += 32) {
            float acc = sb[c];
#pragma unroll
            for (int k = 0; k < Lsz; ++k) acc = fmaf(zr[k], sW[k * Hsz + c], acc);
            g_buf0[(size_t)p * Hsz + c] = lrelu(acc);
        }
    }
}

// ---------------- main GEMM: C = lrelu(A @ W + bias), N=512, K=512 ----------------
// BM=128, BN=128, BK=16, 256 threads, 8x8 microtile, double-buffered smem.
// head=0: rows [0,Bsz). head=1: blockIdx.z = domain d, rows [dstart[d], dstart[d+1]).
__global__ __launch_bounds__(256) void k_gemm512(int srcBuf, int dstBuf,
                                                 const float* __restrict__ Wp,
                                                 const float* __restrict__ bp,
                                                 int head, int wStride, int bStride) {
    const float* __restrict__ A = srcBuf ? g_buf1 : g_buf0;
    float* __restrict__ C = dstBuf ? g_buf1 : g_buf0;

    int d = blockIdx.z;
    int row_lo, row_hi;
    if (head) { row_lo = g_dstart[d]; row_hi = g_dstart[d + 1]; }
    else      { row_lo = 0;           row_hi = Bsz; }
    int rbase = row_lo + blockIdx.y * 128;
    if (rbase >= row_hi) return;

    const float* __restrict__ W = Wp + (size_t)d * wStride;
    const float* __restrict__ bias = bp + (size_t)d * bStride;
    int cb0 = blockIdx.x * 128;

    __shared__ float As[2][16][128];
    __shared__ float Bs[2][16][128];

    int tid = threadIdx.x;
    int tx = tid & 15, ty = tid >> 4;

    // A tile loaders: 128 rows x 4 float4 (16 k) = 512 units; unit lid = i*256+tid
    int ar0 = tid >> 2, ak0 = tid & 3;      // i=0
    int ar1 = ar0 + 64, ak1 = ak0;          // i=1
    // B tile loaders: 16 rows x 32 float4 = 512 units
    int bk0 = tid >> 5, bj0 = tid & 31;     // i=0
    int bk1 = bk0 + 8, bj1 = bj0;           // i=1

    int arow0 = rbase + ar0; if (arow0 >= row_hi) arow0 = row_hi - 1;
    int arow1 = rbase + ar1; if (arow1 >= row_hi) arow1 = row_hi - 1;
    const float4* __restrict__ Ar0 = (const float4*)(A + (size_t)arow0 * Hsz);
    const float4* __restrict__ Ar1 = (const float4*)(A + (size_t)arow1 * Hsz);

    float acc[8][8];
#pragma unroll
    for (int i = 0; i < 8; ++i)
#pragma unroll
        for (int j = 0; j < 8; ++j) acc[i][j] = 0.0f;

    // prologue: load tile kt=0 into stage 0
    {
        float4 va0 = Ar0[ak0];
        float4 va1 = Ar1[ak1];
        float4 vb0 = *(const float4*)(W + (size_t)bk0 * Hsz + cb0 + bj0 * 4);
        float4 vb1 = *(const float4*)(W + (size_t)bk1 * Hsz + cb0 + bj1 * 4);
        As[0][ak0 * 4 + 0][ar0] = va0.x; As[0][ak0 * 4 + 1][ar0] = va0.y;
        As[0][ak0 * 4 + 2][ar0] = va0.z; As[0][ak0 * 4 + 3][ar0] = va0.w;
        As[0][ak1 * 4 + 0][ar1] = va1.x; As[0][ak1 * 4 + 1][ar1] = va1.y;
        As[0][ak1 * 4 + 2][ar1] = va1.z; As[0][ak1 * 4 + 3][ar1] = va1.w;
        *(float4*)&Bs[0][bk0][bj0 * 4] = vb0;
        *(float4*)&Bs[0][bk1][bj1 * 4] = vb1;
    }
    __syncthreads();

    int s = 0;
    for (int kt = 0; kt < 32; ++kt) {
        float4 na0, na1, nb0, nb1;
        if (kt < 31) {
            int ko = (kt + 1) * 4;  // float4 offset within row
            na0 = Ar0[ko + ak0];
            na1 = Ar1[ko + ak1];
            nb0 = *(const float4*)(W + (size_t)((kt + 1) * 16 + bk0) * Hsz + cb0 + bj0 * 4);
            nb1 = *(const float4*)(W + (size_t)((kt + 1) * 16 + bk1) * Hsz + cb0 + bj1 * 4);
        }
#pragma unroll
        for (int kk = 0; kk < 16; ++kk) {
            float a[8], b[8];
            *(float4*)&a[0] = *(const float4*)&As[s][kk][ty * 4];
            *(float4*)&a[4] = *(const float4*)&As[s][kk][64 + ty * 4];
            *(float4*)&b[0] = *(const float4*)&Bs[s][kk][tx * 4];
            *(float4*)&b[4] = *(const float4*)&Bs[s][kk][64 + tx * 4];
#pragma unroll
            for (int i = 0; i < 8; ++i)
#pragma unroll
                for (int j = 0; j < 8; ++j)
                    acc[i][j] = fmaf(a[i], b[j], acc[i][j]);
        }
        if (kt < 31) {
            int ns = s ^ 1;
            As[ns][ak0 * 4 + 0][ar0] = na0.x; As[ns][ak0 * 4 + 1][ar0] = na0.y;
            As[ns][ak0 * 4 + 2][ar0] = na0.z; As[ns][ak0 * 4 + 3][ar0] = na0.w;
            As[ns][ak1 * 4 + 0][ar1] = na1.x; As[ns][ak1 * 4 + 1][ar1] = na1.y;
            As[ns][ak1 * 4 + 2][ar1] = na1.z; As[ns][ak1 * 4 + 3][ar1] = na1.w;
            *(float4*)&Bs[ns][bk0][bj0 * 4] = nb0;
            *(float4*)&Bs[ns][bk1][bj1 * 4] = nb1;
        }
        __syncthreads();
        s ^= 1;
    }

    // epilogue: bias + lrelu, guarded row stores
    float4 bv0 = *(const float4*)(bias + cb0 + tx * 4);
    float4 bv1 = *(const float4*)(bias + cb0 + 64 + tx * 4);
#pragma unroll
    for (int i = 0; i < 8; ++i) {
        int rloc = (i < 4) ? (ty * 4 + i) : (64 + ty * 4 + (i - 4));
        int r = rbase + rloc;
        if (r < row_hi) {
            float4 o;
            o.x = lrelu(acc[i][0] + bv0.x);
            o.y = lrelu(acc[i][1] + bv0.y);
            o.z = lrelu(acc[i][2] + bv0.z);
            o.w = lrelu(acc[i][3] + bv0.w);
            *(float4*)(C + (size_t)r * Hsz + cb0 + tx * 4) = o;
            o.x = lrelu(acc[i][4] + bv1.x);
            o.y = lrelu(acc[i][5] + bv1.y);
            o.z = lrelu(acc[i][6] + bv1.z);
            o.w = lrelu(acc[i][7] + bv1.w);
            *(float4*)(C + (size_t)r * Hsz + cb0 + 64 + tx * 4) = o;
        }
    }
}

// ---------------- final layer: out[perm[r]] = A @ hW3[d] + hb3[d], N=64, no lrelu ----
// BM=128, BN=64, BK=16, 256 threads, 8x4 microtile
__global__ __launch_bounds__(256) void k_gemm_final(int srcBuf,
                                                    const float* __restrict__ Wp,
                                                    const float* __restrict__ bp,
                                                    float* __restrict__ out) {
    const float* __restrict__ A = srcBuf ? g_buf1 : g_buf0;
    int d = blockIdx.z;
    int row_lo = g_dstart[d], row_hi = g_dstart[d + 1];
    int rbase = row_lo + blockIdx.y * 128;
    if (rbase >= row_hi) return;

    const float* __restrict__ W = Wp + (size_t)d * Hsz * Ssz;
    const float* __restrict__ bias = bp + (size_t)d * Ssz;

    __shared__ float As[2][16][128];
    __shared__ float Bs[2][16][64];

    int tid = threadIdx.x;
    int tx = tid & 15, ty = tid >> 4;

    int ar0 = tid >> 2, ak0 = tid & 3;
    int ar1 = ar0 + 64, ak1 = ak0;
    int bk = tid >> 4, bj = tid & 15;  // 16 rows x 16 float4 = 256 units, 1/thread

    int arow0 = rbase + ar0; if (arow0 >= row_hi) arow0 = row_hi - 1;
    int arow1 = rbase + ar1; if (arow1 >= row_hi) arow1 = row_hi - 1;
    const float4* __restrict__ Ar0 = (const float4*)(A + (size_t)arow0 * Hsz);
    const float4* __restrict__ Ar1 = (const float4*)(A + (size_t)arow1 * Hsz);

    float acc[8][4];
#pragma unroll
    for (int i = 0; i < 8; ++i)
#pragma unroll
        for (int j = 0; j < 4; ++j) acc[i][j] = 0.0f;

    {
        float4 va0 = Ar0[ak0];
        float4 va1 = Ar1[ak1];
        float4 vb = *(const float4*)(W + (size_t)bk * Ssz + bj * 4);
        As[0][ak0 * 4 + 0][ar0] = va0.x; As[0][ak0 * 4 + 1][ar0] = va0.y;
        As[0][ak0 * 4 + 2][ar0] = va0.z; As[0][ak0 * 4 + 3][ar0] = va0.w;
        As[0][ak1 * 4 + 0][ar1] = va1.x; As[0][ak1 * 4 + 1][ar1] = va1.y;
        As[0][ak1 * 4 + 2][ar1] = va1.z; As[0][ak1 * 4 + 3][ar1] = va1.w;
        *(float4*)&Bs[0][bk][bj * 4] = vb;
    }
    __syncthreads();

    int s = 0;
    for (int kt = 0; kt < 32; ++kt) {
        float4 na0, na1, nb;
        if (kt < 31) {
            int ko = (kt + 1) * 4;
            na0 = Ar0[ko + ak0];
            na1 = Ar1[ko + ak1];
            nb = *(const float4*)(W + (size_t)((kt + 1) * 16 + bk) * Ssz + bj * 4);
        }
#pragma unroll
        for (int kk = 0; kk < 16; ++kk) {
            float a[8], b[4];
            *(float4*)&a[0] = *(const float4*)&As[s][kk][ty * 4];
            *(float4*)&a[4] = *(const float4*)&As[s][kk][64 + ty * 4];
            *(float4*)&b[0] = *(const float4*)&Bs[s][kk][tx * 4];
#pragma unroll
            for (int i = 0; i < 8; ++i)
#pragma unroll
                for (int j = 0; j < 4; ++j)
                    acc[i][j] = fmaf(a[i], b[j], acc[i][j]);
        }
        if (kt < 31) {
            int ns = s ^ 1;
            As[ns][ak0 * 4 + 0][ar0] = na0.x; As[ns][ak0 * 4 + 1][ar0] = na0.y;
            As[ns][ak0 * 4 + 2][ar0] = na0.z; As[ns][ak0 * 4 + 3][ar0] = na0.w;
            As[ns][ak1 * 4 + 0][ar1] = na1.x; As[ns][ak1 * 4 + 1][ar1] = na1.y;
            As[ns][ak1 * 4 + 2][ar1] = na1.z; As[ns][ak1 * 4 + 3][ar1] = na1.w;
            *(float4*)&Bs[ns][bk][bj * 4] = nb;
        }
        __syncthreads();
        s ^= 1;
    }

    float4 bv = *(const float4*)(bias + tx * 4);
#pragma unroll
    for (int i = 0; i < 8; ++i) {
        int rloc = (i < 4) ? (ty * 4 + i) : (64 + ty * 4 + (i - 4));
        int r = rbase + rloc;
        if (r < row_hi) {
            int ob = g_perm[r];
            float4 o;
            o.x = acc[i][0] + bv.x;
            o.y = acc[i][1] + bv.y;
            o.z = acc[i][2] + bv.z;
            o.w = acc[i][3] + bv.w;
            *(float4*)(out + (size_t)ob * Ssz + tx * 4) = o;
        }
    }
}

// ---------------- launch ----------------
extern "C" void kernel_launch(void* const* d_in, const int* in_sizes, int n_in,
                              void* d_out, int out_size) {
    const float* z   = (const float*)d_in[0];
    const int*   y   = (const int*)d_in[1];
    const float* tW0 = (const float*)d_in[2];
    const float* tb0 = (const float*)d_in[3];
    const float* tW1 = (const float*)d_in[4];
    const float* tb1 = (const float*)d_in[5];
    const float* tW2 = (const float*)d_in[6];
    const float* tb2 = (const float*)d_in[7];
    const float* tW3 = (const float*)d_in[8];
    const float* tb3 = (const float*)d_in[9];
    const float* hW0 = (const float*)d_in[10];
    const float* hb0 = (const float*)d_in[11];
    const float* hW1 = (const float*)d_in[12];
    const float* hb1 = (const float*)d_in[13];
    const float* hW2 = (const float*)d_in[14];
    const float* hb2 = (const float*)d_in[15];
    const float* hW3 = (const float*)d_in[16];
    const float* hb3 = (const float*)d_in[17];
    float* out = (float*)d_out;

    k_zero<<<1, 32>>>();
    k_hist<<<Bsz / 256, 256>>>(y);
    k_prefix<<<1, 1>>>();
    k_scatter<<<Bsz / 256, 256>>>(y);
    k_layer0<<<Bsz / 32, 256>>>(z, tW0, tb0);

    dim3 gT(4, 64, 1);
    k_gemm512<<<gT, 256>>>(0, 1, tW1, tb1, 0, 0, 0);
    k_gemm512<<<gT, 256>>>(1, 0, tW2, tb2, 0, 0, 0);
    k_gemm512<<<gT, 256>>>(0, 1, tW3, tb3, 0, 0, 0);

    dim3 gH(4, 64, Dsz);
    k_gemm512<<<gH, 256>>>(1, 0, hW0, hb0, 1, Hsz * Hsz, Hsz);
    k_gemm512<<<gH, 256>>>(0, 1, hW1, hb1, 1, Hsz * Hsz, Hsz);
    k_gemm512<<<gH, 256>>>(1, 0, hW2, hb2, 1, Hsz * Hsz, Hsz);

    dim3 gF(1, 64, Dsz);
    k_gemm_final<<<gF, 256>>>(0, hW3, hb3, out);
}

// round 4
// speedup vs baseline: 1.6936x; 1.6936x over previous
#include <cuda_runtime.h>
#include <cuda_bf16.h>
#include <cstdint>

#define Bsz 8192
#define Lsz 16
#define Hsz 512
#define Ssz 64
#define Dsz 16

// ---------------- device scratch ----------------
__device__ int g_perm[Bsz];
__device__ int g_dstart[Dsz + 1];
__device__ int g_dcount[Dsz];
__device__ int g_dfill[Dsz];
__device__ int g_tile_d[96];    // 128-row granularity (final layer)
__device__ int g_tile_r0[96];
__device__ int g_ntiles;
__device__ int g_tile2_d[64];   // 256-row granularity (head hidden layers)
__device__ int g_tile2_r0[64];
__device__ int g_ntiles2;

// activations: bf16 hi/lo planes, ping-pong buffers
__device__ __nv_bfloat16 g_aH[2][Bsz * Hsz];
__device__ __nv_bfloat16 g_aL[2][Bsz * Hsz];

// weights: bf16 hi/lo planes, transposed to [N, K] K-major
__device__ __nv_bfloat16 g_tWh[3][Hsz * Hsz];
__device__ __nv_bfloat16 g_tWl[3][Hsz * Hsz];
__device__ __nv_bfloat16 g_hWh[3][Dsz * Hsz * Hsz];
__device__ __nv_bfloat16 g_hWl[3][Dsz * Hsz * Hsz];
__device__ __nv_bfloat16 g_fWh[Dsz * Ssz * Hsz];
__device__ __nv_bfloat16 g_fWl[Dsz * Ssz * Hsz];

__device__ __forceinline__ float lrelu(float x) { return x >= 0.0f ? x : 0.2f * x; }

__device__ __forceinline__ uint32_t smem_u32(const void* p) {
    uint32_t a;
    asm("{ .reg .u64 t; cvta.to.shared.u64 t, %1; cvt.u32.u64 %0, t; }" : "=r"(a) : "l"(p));
    return a;
}

#define CP_ASYNC16(daddr, gp) \
    asm volatile("cp.async.cg.shared.global [%0], [%1], 16;" :: "r"(daddr), "l"(gp))
#define CP_COMMIT() asm volatile("cp.async.commit_group;" ::: "memory")
#define CP_WAIT0() asm volatile("cp.async.wait_group 0;" ::: "memory")

#define LDM4(r0, r1, r2, r3, addr) \
    asm volatile("ldmatrix.sync.aligned.m8n8.x4.shared.b16 {%0,%1,%2,%3}, [%4];" \
                 : "=r"(r0), "=r"(r1), "=r"(r2), "=r"(r3) : "r"(addr))

#define MMA16816(c, a, b0, b1) \
    asm volatile("mma.sync.aligned.m16n8k16.row.col.f32.bf16.bf16.f32 " \
                 "{%0,%1,%2,%3}, {%4,%5,%6,%7}, {%8,%9}, {%0,%1,%2,%3};" \
                 : "+f"((c)[0]), "+f"((c)[1]), "+f"((c)[2]), "+f"((c)[3]) \
                 : "r"((a)[0]), "r"((a)[1]), "r"((a)[2]), "r"((a)[3]), "r"(b0), "r"(b1))

__device__ __forceinline__ uint32_t bfpack(float a, float b) {
    __nv_bfloat16 ha = __float2bfloat16(a), hb = __float2bfloat16(b);
    return (uint32_t)__bfloat16_as_ushort(ha) | ((uint32_t)__bfloat16_as_ushort(hb) << 16);
}

// ---------------- domain bucketing ----------------
__global__ void k_zero() {
    int t = threadIdx.x;
    if (t < Dsz) g_dcount[t] = 0;
}

__global__ void k_hist(const int* __restrict__ y) {
    int i = blockIdx.x * blockDim.x + threadIdx.x;
    if (i < Bsz) atomicAdd(&g_dcount[y[i]], 1);
}

__global__ void k_prefix() {
    int s = 0;
    for (int d = 0; d < Dsz; ++d) {
        g_dstart[d] = s;
        g_dfill[d] = s;
        s += g_dcount[d];
    }
    g_dstart[Dsz] = s;
    int nt = 0;
    for (int d = 0; d < Dsz; ++d)
        for (int r = g_dstart[d]; r < g_dstart[d + 1]; r += 128) {
            g_tile_d[nt] = d; g_tile_r0[nt] = r; nt++;
        }
    g_ntiles = nt;
    int nt2 = 0;
    for (int d = 0; d < Dsz; ++d)
        for (int r = g_dstart[d]; r < g_dstart[d + 1]; r += 256) {
            g_tile2_d[nt2] = d; g_tile2_r0[nt2] = r; nt2++;
        }
    g_ntiles2 = nt2;
}

__global__ void k_scatter(const int* __restrict__ y) {
    int i = blockIdx.x * blockDim.x + threadIdx.x;
    if (i < Bsz) {
        int p = atomicAdd(&g_dfill[y[i]], 1);
        g_perm[p] = i;
    }
}

// ---------------- weight prep: fp32 [K,N] -> bf16 hi/lo [N,K] ----------------
__global__ void k_prep(const float* __restrict__ W, int N, int wsel, int lidx) {
    __shared__ float t[32][33];
    int z = blockIdx.z;
    const float* Wz = W + (size_t)z * Hsz * N;
    __nv_bfloat16 *Th, *Tl;
    if (wsel == 0)      { Th = g_tWh[lidx]; Tl = g_tWl[lidx]; }
    else if (wsel == 1) { size_t o = (size_t)z * Hsz * Hsz; Th = g_hWh[lidx] + o; Tl = g_hWl[lidx] + o; }
    else                { size_t o = (size_t)z * Ssz * Hsz; Th = g_fWh + o; Tl = g_fWl + o; }
    int n0 = blockIdx.x * 32, k0 = blockIdx.y * 32;
    int tx = threadIdx.x, ty = threadIdx.y;
#pragma unroll
    for (int i = 0; i < 4; ++i)
        t[ty + 8 * i][tx] = Wz[(size_t)(k0 + ty + 8 * i) * N + n0 + tx];
    __syncthreads();
#pragma unroll
    for (int i = 0; i < 4; ++i) {
        float v = t[tx][ty + 8 * i];
        int n = n0 + ty + 8 * i, k = k0 + tx;
        __nv_bfloat16 h = __float2bfloat16(v);
        Th[(size_t)n * Hsz + k] = h;
        Tl[(size_t)n * Hsz + k] = __float2bfloat16(v - __bfloat162float(h));
    }
}

// ---------------- layer 0: lrelu(z[perm] @ tW0 + b) -> split hi/lo into buf 0 ----------
__global__ __launch_bounds__(256) void k_layer0(const float* __restrict__ z,
                                                const float* __restrict__ W,
                                                const float* __restrict__ bias) {
    __shared__ float sW[Lsz * Hsz];
    __shared__ float sb[Hsz];
    int tid = threadIdx.x;
    for (int i = tid; i < Lsz * Hsz; i += 256) sW[i] = W[i];
    for (int i = tid; i < Hsz; i += 256) sb[i] = bias[i];
    __syncthreads();

    int w = tid >> 5, lane = tid & 31;
    for (int q = 0; q < 4; ++q) {
        int p = blockIdx.x * 32 + w * 4 + q;
        int b = g_perm[p];
        float zr[Lsz];
#pragma unroll
        for (int k = 0; k < Lsz; ++k) zr[k] = __ldg(&z[b * Lsz + k]);
#pragma unroll
        for (int it = 0; it < 8; ++it) {
            int c = it * 64 + lane * 2;
            float a0 = sb[c], a1 = sb[c + 1];
#pragma unroll
            for (int k = 0; k < Lsz; ++k) {
                a0 = fmaf(zr[k], sW[k * Hsz + c], a0);
                a1 = fmaf(zr[k], sW[k * Hsz + c + 1], a1);
            }
            a0 = lrelu(a0); a1 = lrelu(a1);
            __nv_bfloat16 h0 = __float2bfloat16(a0), h1 = __float2bfloat16(a1);
            float l0 = a0 - __bfloat162float(h0), l1 = a1 - __bfloat162float(h1);
            size_t o = (size_t)p * Hsz + c;
            *(uint32_t*)(&g_aH[0][o]) = (uint32_t)__bfloat16_as_ushort(h0) |
                                        ((uint32_t)__bfloat16_as_ushort(h1) << 16);
            *(uint32_t*)(&g_aL[0][o]) = bfpack(l0, l1);
        }
    }
}

// ---------------- main HMMA GEMM: 256x128 block tile, K=512, bf16x3 split ----------------
// smem layout (dynamic): [0,512) bias; A at 1024: [2 stages][2 planes][32768];
// B at 132096: [2 stages][2 planes][16384]. total 197632.
#define SM_A_OFF 1024
#define SM_B_OFF 132096
#define SMEM_MAIN 197632

__global__ __launch_bounds__(512) void k_hmma(int src, int dst, int wsel, int lidx,
                                              const float* __restrict__ bias,
                                              int bStride, int headMode) {
    extern __shared__ char sm[];
    int tid = threadIdx.x;
    int t = blockIdx.y;
    int d, rbase, row_hi;
    if (headMode) {
        if (t >= g_ntiles2) return;
        d = g_tile2_d[t]; rbase = g_tile2_r0[t]; row_hi = g_dstart[d + 1];
    } else {
        d = 0; rbase = t * 256; row_hi = Bsz;
    }
    int cb0 = blockIdx.x * 128;
    int rclamp = row_hi - 1;

    const __nv_bfloat16* aH = g_aH[src];
    const __nv_bfloat16* aL = g_aL[src];
    __nv_bfloat16* oH = g_aH[dst];
    __nv_bfloat16* oL = g_aL[dst];
    const __nv_bfloat16 *Wh, *Wl;
    if (wsel == 0) { Wh = g_tWh[lidx]; Wl = g_tWl[lidx]; }
    else { size_t o = (size_t)d * Hsz * Hsz; Wh = g_hWh[lidx] + o; Wl = g_hWl[lidx] + o; }
    Wh += (size_t)cb0 * Hsz;
    Wl += (size_t)cb0 * Hsz;
    const float* bp = bias + (size_t)d * bStride + cb0;

    float* sbias = (float*)sm;
    if (tid < 128) sbias[tid] = bp[tid];
    uint32_t sbase = smem_u32(sm);

    int wid = tid >> 5, lane = tid & 31;
    int wr = wid >> 2, wc = wid & 3;
    int m0 = wr * 64, n0w = wc * 32;

    float acc[4][4][4];
#pragma unroll
    for (int i = 0; i < 4; ++i)
#pragma unroll
        for (int j = 0; j < 4; ++j)
#pragma unroll
            for (int k = 0; k < 4; ++k) acc[i][j][k] = 0.0f;

    // issue helpers (stage st)
#define ISSUE_A(kc, st) do { \
    _Pragma("unroll") \
    for (int i = 0; i < 8; ++i) { \
        int tt = i * 512 + tid; \
        int plane = tt >> 11; \
        int row = (tt >> 3) & 255; \
        int seg = tt & 7; \
        int rg = rbase + row; if (rg > rclamp) rg = rclamp; \
        const __nv_bfloat16* gp = (plane ? aL : aH) + (size_t)rg * Hsz + (kc) * 64 + seg * 8; \
        uint32_t da = sbase + SM_A_OFF + (st) * 65536 + plane * 32768 + row * 128 + \
                      (((seg ^ (row & 7))) << 4); \
        CP_ASYNC16(da, gp); \
    } } while (0)

#define ISSUE_B(kc, st) do { \
    _Pragma("unroll") \
    for (int i = 0; i < 4; ++i) { \
        int tt = i * 512 + tid; \
        int plane = tt >> 10; \
        int row = (tt >> 3) & 127; \
        int seg = tt & 7; \
        const __nv_bfloat16* gp = (plane ? Wl : Wh) + (size_t)row * Hsz + (kc) * 64 + seg * 8; \
        uint32_t da = sbase + SM_B_OFF + (st) * 32768 + plane * 16384 + row * 128 + \
                      (((seg ^ (row & 7))) << 4); \
        CP_ASYNC16(da, gp); \
    } } while (0)

    ISSUE_A(0, 0); ISSUE_B(0, 0);
    CP_COMMIT();
    CP_WAIT0();
    __syncthreads();

    for (int kc = 0; kc < 8; ++kc) {
        int st = kc & 1;
        if (kc < 7) {
            ISSUE_A(kc + 1, st ^ 1);
            ISSUE_B(kc + 1, st ^ 1);
            CP_COMMIT();
        }
        uint32_t aBase = sbase + SM_A_OFF + st * 65536;
        uint32_t bBase = sbase + SM_B_OFF + st * 32768;
#pragma unroll
        for (int j = 0; j < 4; ++j) {
            uint32_t bh[4][2], bl[4][2], af[4][4];
            int kb = (lane >> 4);  // which k8 half this lane fetches
#pragma unroll
            for (int nt = 0; nt < 2; ++nt) {
                int lrow = n0w + nt * 16 + (lane & 15);
                uint32_t addr = bBase + lrow * 128 + (((j * 2 + kb) ^ (lrow & 7)) << 4);
                uint32_t r0, r1, r2, r3;
                LDM4(r0, r1, r2, r3, addr);
                bh[nt * 2][0] = r0; bh[nt * 2][1] = r2;
                bh[nt * 2 + 1][0] = r1; bh[nt * 2 + 1][1] = r3;
                LDM4(r0, r1, r2, r3, addr + 16384);
                bl[nt * 2][0] = r0; bl[nt * 2][1] = r2;
                bl[nt * 2 + 1][0] = r1; bl[nt * 2 + 1][1] = r3;
            }
#pragma unroll
            for (int ti = 0; ti < 4; ++ti) {
                int lrow = m0 + ti * 16 + (lane & 15);
                uint32_t addr = aBase + lrow * 128 + (((j * 2 + kb) ^ (lrow & 7)) << 4);
                LDM4(af[ti][0], af[ti][1], af[ti][2], af[ti][3], addr);
            }
#pragma unroll
            for (int mi = 0; mi < 4; ++mi)
#pragma unroll
                for (int nj = 0; nj < 4; ++nj) {
                    MMA16816(acc[mi][nj], af[mi], bh[nj][0], bh[nj][1]);
                    MMA16816(acc[mi][nj], af[mi], bl[nj][0], bl[nj][1]);
                }
#pragma unroll
            for (int ti = 0; ti < 4; ++ti) {
                int lrow = m0 + ti * 16 + (lane & 15);
                uint32_t addr = aBase + 32768 + lrow * 128 + (((j * 2 + kb) ^ (lrow & 7)) << 4);
                LDM4(af[ti][0], af[ti][1], af[ti][2], af[ti][3], addr);
            }
#pragma unroll
            for (int mi = 0; mi < 4; ++mi)
#pragma unroll
                for (int nj = 0; nj < 4; ++nj)
                    MMA16816(acc[mi][nj], af[mi], bh[nj][0], bh[nj][1]);
        }
        if (kc < 7) CP_WAIT0();
        __syncthreads();
    }

    // epilogue: bias + lrelu, split to hi/lo bf16, store
#pragma unroll
    for (int mi = 0; mi < 4; ++mi)
#pragma unroll
        for (int half = 0; half < 2; ++half) {
            int r = rbase + m0 + mi * 16 + (lane >> 2) + half * 8;
            if (r < row_hi) {
#pragma unroll
                for (int nj = 0; nj < 4; ++nj) {
                    int cl = n0w + nj * 8 + (lane & 3) * 2;
                    float v0 = lrelu(acc[mi][nj][half * 2 + 0] + sbias[cl]);
                    float v1 = lrelu(acc[mi][nj][half * 2 + 1] + sbias[cl + 1]);
                    __nv_bfloat16 h0 = __float2bfloat16(v0), h1 = __float2bfloat16(v1);
                    float l0 = v0 - __bfloat162float(h0), l1 = v1 - __bfloat162float(h1);
                    size_t o = (size_t)r * Hsz + cb0 + cl;
                    *(uint32_t*)(&oH[o]) = (uint32_t)__bfloat16_as_ushort(h0) |
                                           ((uint32_t)__bfloat16_as_ushort(h1) << 16);
                    *(uint32_t*)(&oL[o]) = bfpack(l0, l1);
                }
            }
        }
#undef ISSUE_A
#undef ISSUE_B
}

// ---------------- final layer: 128x64 tile, scatter to out[perm] ----------------
// smem: [0,256) bias; A at 1024: [2][2][16384]; B at 66560: [2][2][8192]. total 99328.
#define FSM_A_OFF 1024
#define FSM_B_OFF 66560
#define SMEM_FIN 99328

__global__ __launch_bounds__(256) void k_fin(int src, const float* __restrict__ bias,
                                             float* __restrict__ out) {
    extern __shared__ char sm[];
    int tid = threadIdx.x;
    int t = blockIdx.y;
    if (t >= g_ntiles) return;
    int d = g_tile_d[t];
    int rbase = g_tile_r0[t];
    int row_hi = g_dstart[d + 1];
    int rclamp = row_hi - 1;

    const __nv_bfloat16* aH = g_aH[src];
    const __nv_bfloat16* aL = g_aL[src];
    const __nv_bfloat16* Wh = g_fWh + (size_t)d * Ssz * Hsz;
    const __nv_bfloat16* Wl = g_fWl + (size_t)d * Ssz * Hsz;
    const float* bp = bias + (size_t)d * Ssz;

    float* sbias = (float*)sm;
    if (tid < 64) sbias[tid] = bp[tid];
    uint32_t sbase = smem_u32(sm);

    int wid = tid >> 5, lane = tid & 31;
    int wr = wid >> 2, wc = wid & 3;
    int m0 = wr * 64, n0w = wc * 16;

    float acc[4][2][4];
#pragma unroll
    for (int i = 0; i < 4; ++i)
#pragma unroll
        for (int j = 0; j < 2; ++j)
#pragma unroll
            for (int k = 0; k < 4; ++k) acc[i][j][k] = 0.0f;

#define FISSUE_A(kc, st) do { \
    _Pragma("unroll") \
    for (int i = 0; i < 8; ++i) { \
        int tt = i * 256 + tid; \
        int plane = tt >> 10; \
        int row = (tt >> 3) & 127; \
        int seg = tt & 7; \
        int rg = rbase + row; if (rg > rclamp) rg = rclamp; \
        const __nv_bfloat16* gp = (plane ? aL : aH) + (size_t)rg * Hsz + (kc) * 64 + seg * 8; \
        uint32_t da = sbase + FSM_A_OFF + (st) * 32768 + plane * 16384 + row * 128 + \
                      (((seg ^ (row & 7))) << 4); \
        CP_ASYNC16(da, gp); \
    } } while (0)

#define FISSUE_B(kc, st) do { \
    _Pragma("unroll") \
    for (int i = 0; i < 4; ++i) { \
        int tt = i * 256 + tid; \
        int plane = tt >> 9; \
        int row = (tt >> 3) & 63; \
        int seg = tt & 7; \
        const __nv_bfloat16* gp = (plane ? Wl : Wh) + (size_t)row * Hsz + (kc) * 64 + seg * 8; \
        uint32_t da = sbase + FSM_B_OFF + (st) * 16384 + plane * 8192 + row * 128 + \
                      (((seg ^ (row & 7))) << 4); \
        CP_ASYNC16(da, gp); \
    } } while (0)

    FISSUE_A(0, 0); FISSUE_B(0, 0);
    CP_COMMIT();
    CP_WAIT0();
    __syncthreads();

    for (int kc = 0; kc < 8; ++kc) {
        int st = kc & 1;
        if (kc < 7) {
            FISSUE_A(kc + 1, st ^ 1);
            FISSUE_B(kc + 1, st ^ 1);
            CP_COMMIT();
        }
        uint32_t aBase = sbase + FSM_A_OFF + st * 32768;
        uint32_t bBase = sbase + FSM_B_OFF + st * 16384;
#pragma unroll
        for (int j = 0; j < 4; ++j) {
            uint32_t bh[2][2], bl[2][2], af[4][4];
            int kb = (lane >> 4);
            {
                int lrow = n0w + (lane & 15);
                uint32_t addr = bBase + lrow * 128 + (((j * 2 + kb) ^ (lrow & 7)) << 4);
                uint32_t r0, r1, r2, r3;
                LDM4(r0, r1, r2, r3, addr);
                bh[0][0] = r0; bh[0][1] = r2; bh[1][0] = r1; bh[1][1] = r3;
                LDM4(r0, r1, r2, r3, addr + 8192);
                bl[0][0] = r0; bl[0][1] = r2; bl[1][0] = r1; bl[1][1] = r3;
            }
#pragma unroll
            for (int ti = 0; ti < 4; ++ti) {
                int lrow = m0 + ti * 16 + (lane & 15);
                uint32_t addr = aBase + lrow * 128 + (((j * 2 + kb) ^ (lrow & 7)) << 4);
                LDM4(af[ti][0], af[ti][1], af[ti][2], af[ti][3], addr);
            }
#pragma unroll
            for (int mi = 0; mi < 4; ++mi)
#pragma unroll
                for (int nj = 0; nj < 2; ++nj) {
                    MMA16816(acc[mi][nj], af[mi], bh[nj][0], bh[nj][1]);
                    MMA16816(acc[mi][nj], af[mi], bl[nj][0], bl[nj][1]);
                }
#pragma unroll
            for (int ti = 0; ti < 4; ++ti) {
                int lrow = m0 + ti * 16 + (lane & 15);
                uint32_t addr = aBase + 16384 + lrow * 128 + (((j * 2 + kb) ^ (lrow & 7)) << 4);
                LDM4(af[ti][0], af[ti][1], af[ti][2], af[ti][3], addr);
            }
#pragma unroll
            for (int mi = 0; mi < 4; ++mi)
#pragma unroll
                for (int nj = 0; nj < 2; ++nj)
                    MMA16816(acc[mi][nj], af[mi], bh[nj][0], bh[nj][1]);
        }
        if (kc < 7) CP_WAIT0();
        __syncthreads();
    }

#pragma unroll
    for (int mi = 0; mi < 4; ++mi)
#pragma unroll
        for (int half = 0; half < 2; ++half) {
            int r = rbase + m0 + mi * 16 + (lane >> 2) + half * 8;
            if (r < row_hi) {
                int ob = g_perm[r];
#pragma unroll
                for (int nj = 0; nj < 2; ++nj) {
                    int cl = n0w + nj * 8 + (lane & 3) * 2;
                    float2 o;
                    o.x = acc[mi][nj][half * 2 + 0] + sbias[cl];
                    o.y = acc[mi][nj][half * 2 + 1] + sbias[cl + 1];
                    *(float2*)(out + (size_t)ob * Ssz + cl) = o;
                }
            }
        }
#undef FISSUE_A
#undef FISSUE_B
}

// ---------------- launch ----------------
extern "C" void kernel_launch(void* const* d_in, const int* in_sizes, int n_in,
                              void* d_out, int out_size) {
    const float* z   = (const float*)d_in[0];
    const int*   y   = (const int*)d_in[1];
    const float* tW0 = (const float*)d_in[2];
    const float* tb0 = (const float*)d_in[3];
    const float* tW1 = (const float*)d_in[4];
    const float* tb1 = (const float*)d_in[5];
    const float* tW2 = (const float*)d_in[6];
    const float* tb2 = (const float*)d_in[7];
    const float* tW3 = (const float*)d_in[8];
    const float* tb3 = (const float*)d_in[9];
    const float* hW0 = (const float*)d_in[10];
    const float* hb0 = (const float*)d_in[11];
    const float* hW1 = (const float*)d_in[12];
    const float* hb1 = (const float*)d_in[13];
    const float* hW2 = (const float*)d_in[14];
    const float* hb2 = (const float*)d_in[15];
    const float* hW3 = (const float*)d_in[16];
    const float* hb3 = (const float*)d_in[17];
    float* out = (float*)d_out;

    cudaFuncSetAttribute(k_hmma, cudaFuncAttributeMaxDynamicSharedMemorySize, SMEM_MAIN);
    cudaFuncSetAttribute(k_fin, cudaFuncAttributeMaxDynamicSharedMemorySize, SMEM_FIN);

    k_zero<<<1, 32>>>();
    k_hist<<<Bsz / 256, 256>>>(y);
    k_prefix<<<1, 1>>>();
    k_scatter<<<Bsz / 256, 256>>>(y);

    dim3 tb(32, 8);
    k_prep<<<dim3(16, 16, 1), tb>>>(tW1, Hsz, 0, 0);
    k_prep<<<dim3(16, 16, 1), tb>>>(tW2, Hsz, 0, 1);
    k_prep<<<dim3(16, 16, 1), tb>>>(tW3, Hsz, 0, 2);
    k_prep<<<dim3(16, 16, Dsz), tb>>>(hW0, Hsz, 1, 0);
    k_prep<<<dim3(16, 16, Dsz), tb>>>(hW1, Hsz, 1, 1);
    k_prep<<<dim3(16, 16, Dsz), tb>>>(hW2, Hsz, 1, 2);
    k_prep<<<dim3(2, 16, Dsz), tb>>>(hW3, Ssz, 2, 0);

    k_layer0<<<Bsz / 32, 256>>>(z, tW0, tb0);

    // trunk: buf0 -> buf1 -> buf0 -> buf1
    k_hmma<<<dim3(4, 32), 512, SMEM_MAIN>>>(0, 1, 0, 0, tb1, 0, 0);
    k_hmma<<<dim3(4, 32), 512, SMEM_MAIN>>>(1, 0, 0, 1, tb2, 0, 0);
    k_hmma<<<dim3(4, 32), 512, SMEM_MAIN>>>(0, 1, 0, 2, tb3, 0, 0);
    // heads: buf1 -> buf0 -> buf1 -> buf0
    k_hmma<<<dim3(4, 48), 512, SMEM_MAIN>>>(1, 0, 1, 0, hb0, Hsz, 1);
    k_hmma<<<dim3(4, 48), 512, SMEM_MAIN>>>(0, 1, 1, 1, hb1, Hsz, 1);
    k_hmma<<<dim3(4, 48), 512, SMEM_MAIN>>>(1, 0, 1, 2, hb2, Hsz, 1);
    // final: buf0 -> out
    k_fin<<<dim3(1, 96), 256, SMEM_FIN>>>(0, hb3, out);
}

// round 5
// speedup vs baseline: 1.9445x; 1.1481x over previous
#include <cuda_runtime.h>
#include <cuda_bf16.h>
#include <cstdint>

#define Bsz 8192
#define Lsz 16
#define Hsz 512
#define Ssz 64
#define Dsz 16

// ---------------- device scratch ----------------
__device__ int g_perm[Bsz];
__device__ int g_dstart[Dsz + 1];
__device__ int g_tile_d[96];    // 128-row granularity tiles (heads + final)
__device__ int g_tile_r0[96];
__device__ int g_ntiles;

// activations: bf16 hi/lo planes, ping-pong buffers
__device__ __nv_bfloat16 g_aH[2][Bsz * Hsz];
__device__ __nv_bfloat16 g_aL[2][Bsz * Hsz];

// weights: bf16 hi/lo planes, transposed to [N, K] K-major
__device__ __nv_bfloat16 g_tWh[3][Hsz * Hsz];
__device__ __nv_bfloat16 g_tWl[3][Hsz * Hsz];
__device__ __nv_bfloat16 g_hWh[3][Dsz * Hsz * Hsz];
__device__ __nv_bfloat16 g_hWl[3][Dsz * Hsz * Hsz];
__device__ __nv_bfloat16 g_fWh[Dsz * Ssz * Hsz];
__device__ __nv_bfloat16 g_fWl[Dsz * Ssz * Hsz];

__device__ __forceinline__ float lrelu(float x) { return x >= 0.0f ? x : 0.2f * x; }

__device__ __forceinline__ uint32_t smem_u32(const void* p) {
    uint32_t a;
    asm("{ .reg .u64 t; cvta.to.shared.u64 t, %1; cvt.u32.u64 %0, t; }" : "=r"(a) : "l"(p));
    return a;
}

#define CP_ASYNC16(daddr, gp) \
    asm volatile("cp.async.cg.shared.global [%0], [%1], 16;" :: "r"(daddr), "l"(gp))
#define CP_COMMIT() asm volatile("cp.async.commit_group;" ::: "memory")
#define CP_WAIT0() asm volatile("cp.async.wait_group 0;" ::: "memory")

#define LDM4(r0, r1, r2, r3, addr) \
    asm volatile("ldmatrix.sync.aligned.m8n8.x4.shared.b16 {%0,%1,%2,%3}, [%4];" \
                 : "=r"(r0), "=r"(r1), "=r"(r2), "=r"(r3) : "r"(addr))

#define MMA16816(c, a, b0, b1) \
    asm volatile("mma.sync.aligned.m16n8k16.row.col.f32.bf16.bf16.f32 " \
                 "{%0,%1,%2,%3}, {%4,%5,%6,%7}, {%8,%9}, {%0,%1,%2,%3};" \
                 : "+f"((c)[0]), "+f"((c)[1]), "+f"((c)[2]), "+f"((c)[3]) \
                 : "r"((a)[0]), "r"((a)[1]), "r"((a)[2]), "r"((a)[3]), "r"(b0), "r"(b1))

__device__ __forceinline__ uint32_t bfpack(float a, float b) {
    __nv_bfloat16 ha = __float2bfloat16(a), hb = __float2bfloat16(b);
    return (uint32_t)__bfloat16_as_ushort(ha) | ((uint32_t)__bfloat16_as_ushort(hb) << 16);
}

// ---------------- fused bucketing: hist + prefix + scatter + tile list ----------------
__global__ __launch_bounds__(1024) void k_bucket(const int* __restrict__ y) {
    __shared__ int cnt[Dsz];
    __shared__ int off[Dsz];
    int tid = threadIdx.x;
    if (tid < Dsz) cnt[tid] = 0;
    __syncthreads();
    for (int i = tid; i < Bsz; i += 1024) atomicAdd(&cnt[y[i]], 1);
    __syncthreads();
    if (tid == 0) {
        int s = 0;
        int nt = 0;
        for (int d = 0; d < Dsz; ++d) {
            g_dstart[d] = s;
            off[d] = s;
            for (int r = s; r < s + cnt[d]; r += 128) {
                g_tile_d[nt] = d;
                g_tile_r0[nt] = r;
                nt++;
            }
            s += cnt[d];
        }
        g_dstart[Dsz] = s;
        g_ntiles = nt;
    }
    __syncthreads();
    for (int i = tid; i < Bsz; i += 1024) {
        int p = atomicAdd(&off[y[i]], 1);
        g_perm[p] = i;
    }
}

// ---------------- unified weight prep: fp32 [K,N] -> bf16 hi/lo [N,K] ----------------
// grid.x = 13568 linear blocks, block = (32,8)
__global__ void k_prep_all(const float* __restrict__ tW1, const float* __restrict__ tW2,
                           const float* __restrict__ tW3, const float* __restrict__ hW0,
                           const float* __restrict__ hW1, const float* __restrict__ hW2,
                           const float* __restrict__ hW3) {
    __shared__ float t[32][33];
    int gid = blockIdx.x;
    const float* W;
    __nv_bfloat16 *Th, *Tl;
    int N, bx, by;
    if (gid < 768) {
        int l = gid >> 8, rem = gid & 255;
        bx = rem & 15; by = rem >> 4;
        W = (l == 0) ? tW1 : (l == 1) ? tW2 : tW3;
        N = Hsz;
        Th = g_tWh[l]; Tl = g_tWl[l];
    } else if (gid < 13056) {
        int q = gid - 768;
        int l = q / 4096;
        int q2 = q & 4095;
        int z = q2 >> 8, rem = q2 & 255;
        bx = rem & 15; by = rem >> 4;
        const float* base = (l == 0) ? hW0 : (l == 1) ? hW1 : hW2;
        W = base + (size_t)z * Hsz * Hsz;
        N = Hsz;
        size_t o = (size_t)z * Hsz * Hsz;
        Th = g_hWh[l] + o; Tl = g_hWl[l] + o;
    } else {
        int q = gid - 13056;
        int z = q >> 5, rem = q & 31;
        bx = rem & 1; by = rem >> 1;
        W = hW3 + (size_t)z * Hsz * Ssz;
        N = Ssz;
        size_t o = (size_t)z * Ssz * Hsz;
        Th = g_fWh + o; Tl = g_fWl + o;
    }
    int n0 = bx * 32, k0 = by * 32;
    int tx = threadIdx.x, ty = threadIdx.y;
#pragma unroll
    for (int i = 0; i < 4; ++i)
        t[ty + 8 * i][tx] = W[(size_t)(k0 + ty + 8 * i) * N + n0 + tx];
    __syncthreads();
#pragma unroll
    for (int i = 0; i < 4; ++i) {
        float v = t[tx][ty + 8 * i];
        int n = n0 + ty + 8 * i, k = k0 + tx;
        __nv_bfloat16 h = __float2bfloat16(v);
        Th[(size_t)n * Hsz + k] = h;
        Tl[(size_t)n * Hsz + k] = __float2bfloat16(v - __bfloat162float(h));
    }
}

// ---------------- layer 0: lrelu(z[perm] @ tW0 + b) -> split hi/lo into buf 0 ----------
__global__ __launch_bounds__(256) void k_layer0(const float* __restrict__ z,
                                                const float* __restrict__ W,
                                                const float* __restrict__ bias) {
    __shared__ float sW[Lsz * Hsz];
    __shared__ float sb[Hsz];
    int tid = threadIdx.x;
    for (int i = tid; i < Lsz * Hsz; i += 256) sW[i] = W[i];
    for (int i = tid; i < Hsz; i += 256) sb[i] = bias[i];
    __syncthreads();

    int w = tid >> 5, lane = tid & 31;
    for (int q = 0; q < 4; ++q) {
        int p = blockIdx.x * 32 + w * 4 + q;
        int b = g_perm[p];
        float zr[Lsz];
#pragma unroll
        for (int k = 0; k < Lsz; ++k) zr[k] = __ldg(&z[b * Lsz + k]);
#pragma unroll
        for (int it = 0; it < 8; ++it) {
            int c = it * 64 + lane * 2;
            float a0 = sb[c], a1 = sb[c + 1];
#pragma unroll
            for (int k = 0; k < Lsz; ++k) {
                a0 = fmaf(zr[k], sW[k * Hsz + c], a0);
                a1 = fmaf(zr[k], sW[k * Hsz + c + 1], a1);
            }
            a0 = lrelu(a0); a1 = lrelu(a1);
            __nv_bfloat16 h0 = __float2bfloat16(a0), h1 = __float2bfloat16(a1);
            float l0 = a0 - __bfloat162float(h0), l1 = a1 - __bfloat162float(h1);
            size_t o = (size_t)p * Hsz + c;
            *(uint32_t*)(&g_aH[0][o]) = (uint32_t)__bfloat16_as_ushort(h0) |
                                        ((uint32_t)__bfloat16_as_ushort(h1) << 16);
            *(uint32_t*)(&g_aL[0][o]) = bfpack(l0, l1);
        }
    }
}

// ---------------- HMMA GEMM: 128x128 block tile, 256 threads, K=512, bf16x3 ----------------
// smem: [0,512) bias; A @1024: [2 stages][2 planes][16384]; B @66560: [2 planes][16384].
// total 99328 (~97KB) -> 2 CTAs/SM if regs <= 128.
#define SM_A_OFF 1024
#define SM_B_OFF 66560
#define SMEM_MAIN 99328

__global__ __launch_bounds__(256) void k_hmma(int src, int dst, int wsel, int lidx,
                                              const float* __restrict__ bias,
                                              int bStride, int headMode) {
    extern __shared__ char sm[];
    int tid = threadIdx.x;
    int t = blockIdx.y;
    int d, rbase, row_hi;
    if (headMode) {
        if (t >= g_ntiles) return;
        d = g_tile_d[t]; rbase = g_tile_r0[t]; row_hi = g_dstart[d + 1];
    } else {
        d = 0; rbase = t * 128; row_hi = Bsz;
    }
    int cb0 = blockIdx.x * 128;
    int rclamp = row_hi - 1;

    const __nv_bfloat16* aH = g_aH[src];
    const __nv_bfloat16* aL = g_aL[src];
    __nv_bfloat16* oH = g_aH[dst];
    __nv_bfloat16* oL = g_aL[dst];
    const __nv_bfloat16 *Wh, *Wl;
    if (wsel == 0) { Wh = g_tWh[lidx]; Wl = g_tWl[lidx]; }
    else { size_t o = (size_t)d * Hsz * Hsz; Wh = g_hWh[lidx] + o; Wl = g_hWl[lidx] + o; }
    Wh += (size_t)cb0 * Hsz;
    Wl += (size_t)cb0 * Hsz;
    const float* bp = bias + (size_t)d * bStride + cb0;

    float* sbias = (float*)sm;
    if (tid < 128) sbias[tid] = bp[tid];
    uint32_t sbase = smem_u32(sm);

    int wid = tid >> 5, lane = tid & 31;
    int wr = wid >> 2, wc = wid & 3;           // 2 x 4 warp grid
    int m0 = wr * 64, n0w = wc * 32;           // warp tile 64 x 32

    float acc[4][4][4];
#pragma unroll
    for (int i = 0; i < 4; ++i)
#pragma unroll
        for (int j = 0; j < 4; ++j)
#pragma unroll
            for (int k = 0; k < 4; ++k) acc[i][j][k] = 0.0f;

    // A tile copy: 2 planes x 128 rows x 8 segs = 2048 segs, 8/thread
#define ISSUE_A(kc, st) do { \
    _Pragma("unroll") \
    for (int i = 0; i < 8; ++i) { \
        int tt = i * 256 + tid; \
        int plane = tt >> 10; \
        int row = (tt >> 3) & 127; \
        int seg = tt & 7; \
        int rg = rbase + row; if (rg > rclamp) rg = rclamp; \
        const __nv_bfloat16* gp = (plane ? aL : aH) + (size_t)rg * Hsz + (kc) * 64 + seg * 8; \
        uint32_t da = sbase + SM_A_OFF + (st) * 32768 + plane * 16384 + row * 128 + \
                      (((seg ^ (row & 7))) << 4); \
        CP_ASYNC16(da, gp); \
    } } while (0)

    // B tile copy: 2 planes x 128 rows x 8 segs = 2048 segs, 8/thread (single buffer)
#define ISSUE_B(kc) do { \
    _Pragma("unroll") \
    for (int i = 0; i < 8; ++i) { \
        int tt = i * 256 + tid; \
        int plane = tt >> 10; \
        int row = (tt >> 3) & 127; \
        int seg = tt & 7; \
        const __nv_bfloat16* gp = (plane ? Wl : Wh) + (size_t)row * Hsz + (kc) * 64 + seg * 8; \
        uint32_t da = sbase + SM_B_OFF + plane * 16384 + row * 128 + \
                      (((seg ^ (row & 7))) << 4); \
        CP_ASYNC16(da, gp); \
    } } while (0)

    ISSUE_A(0, 0); ISSUE_B(0);
    CP_COMMIT();
    CP_WAIT0();
    __syncthreads();

    for (int kc = 0; kc < 8; ++kc) {
        int st = kc & 1;
        if (kc < 7) {
            ISSUE_A(kc + 1, st ^ 1);   // overlaps with compute below
            CP_COMMIT();
        }
        uint32_t aBase = sbase + SM_A_OFF + st * 32768;
        uint32_t bBase = sbase + SM_B_OFF;
#pragma unroll
        for (int j = 0; j < 4; ++j) {
            uint32_t bh[4][2], bl[4][2], af[4][4];
            int kb = (lane >> 4);
#pragma unroll
            for (int nt = 0; nt < 2; ++nt) {
                int lrow = n0w + nt * 16 + (lane & 15);
                uint32_t addr = bBase + lrow * 128 + (((j * 2 + kb) ^ (lrow & 7)) << 4);
                uint32_t r0, r1, r2, r3;
                LDM4(r0, r1, r2, r3, addr);
                bh[nt * 2][0] = r0; bh[nt * 2][1] = r2;
                bh[nt * 2 + 1][0] = r1; bh[nt * 2 + 1][1] = r3;
                LDM4(r0, r1, r2, r3, addr + 16384);
                bl[nt * 2][0] = r0; bl[nt * 2][1] = r2;
                bl[nt * 2 + 1][0] = r1; bl[nt * 2 + 1][1] = r3;
            }
#pragma unroll
            for (int ti = 0; ti < 4; ++ti) {
                int lrow = m0 + ti * 16 + (lane & 15);
                uint32_t addr = aBase + lrow * 128 + (((j * 2 + kb) ^ (lrow & 7)) << 4);
                LDM4(af[ti][0], af[ti][1], af[ti][2], af[ti][3], addr);
            }
#pragma unroll
            for (int mi = 0; mi < 4; ++mi)
#pragma unroll
                for (int nj = 0; nj < 4; ++nj) {
                    MMA16816(acc[mi][nj], af[mi], bh[nj][0], bh[nj][1]);
                    MMA16816(acc[mi][nj], af[mi], bl[nj][0], bl[nj][1]);
                }
#pragma unroll
            for (int ti = 0; ti < 4; ++ti) {
                int lrow = m0 + ti * 16 + (lane & 15);
                uint32_t addr = aBase + 16384 + lrow * 128 + (((j * 2 + kb) ^ (lrow & 7)) << 4);
                LDM4(af[ti][0], af[ti][1], af[ti][2], af[ti][3], addr);
            }
#pragma unroll
            for (int mi = 0; mi < 4; ++mi)
#pragma unroll
                for (int nj = 0; nj < 4; ++nj)
                    MMA16816(acc[mi][nj], af[mi], bh[nj][0], bh[nj][1]);
        }
        __syncthreads();           // all warps done reading B
        if (kc < 7) {
            ISSUE_B(kc + 1);       // refill single B buffer
            CP_COMMIT();
            CP_WAIT0();            // A(kc+1) long done; B exposure ~1 L2 trip
            __syncthreads();
        }
    }

    // epilogue: bias + lrelu, split to hi/lo bf16, store
#pragma unroll
    for (int mi = 0; mi < 4; ++mi)
#pragma unroll
        for (int half = 0; half < 2; ++half) {
            int r = rbase + m0 + mi * 16 + (lane >> 2) + half * 8;
            if (r < row_hi) {
#pragma unroll
                for (int nj = 0; nj < 4; ++nj) {
                    int cl = n0w + nj * 8 + (lane & 3) * 2;
                    float v0 = lrelu(acc[mi][nj][half * 2 + 0] + sbias[cl]);
                    float v1 = lrelu(acc[mi][nj][half * 2 + 1] + sbias[cl + 1]);
                    __nv_bfloat16 h0 = __float2bfloat16(v0), h1 = __float2bfloat16(v1);
                    float l0 = v0 - __bfloat162float(h0), l1 = v1 - __bfloat162float(h1);
                    size_t o = (size_t)r * Hsz + cb0 + cl;
                    *(uint32_t*)(&oH[o]) = (uint32_t)__bfloat16_as_ushort(h0) |
                                           ((uint32_t)__bfloat16_as_ushort(h1) << 16);
                    *(uint32_t*)(&oL[o]) = bfpack(l0, l1);
                }
            }
        }
#undef ISSUE_A
#undef ISSUE_B
}

// ---------------- final layer: 128x64 tile, scatter to out[perm] ----------------
// smem: [0,256) bias; A @1024: [2][2][16384]; B @66560: [2][8192]. total 82944.
#define FSM_A_OFF 1024
#define FSM_B_OFF 66560
#define SMEM_FIN 82944

__global__ __launch_bounds__(256) void k_fin(int src, const float* __restrict__ bias,
                                             float* __restrict__ out) {
    extern __shared__ char sm[];
    int tid = threadIdx.x;
    int t = blockIdx.y;
    if (t >= g_ntiles) return;
    int d = g_tile_d[t];
    int rbase = g_tile_r0[t];
    int row_hi = g_dstart[d + 1];
    int rclamp = row_hi - 1;

    const __nv_bfloat16* aH = g_aH[src];
    const __nv_bfloat16* aL = g_aL[src];
    const __nv_bfloat16* Wh = g_fWh + (size_t)d * Ssz * Hsz;
    const __nv_bfloat16* Wl = g_fWl + (size_t)d * Ssz * Hsz;
    const float* bp = bias + (size_t)d * Ssz;

    float* sbias = (float*)sm;
    if (tid < 64) sbias[tid] = bp[tid];
    uint32_t sbase = smem_u32(sm);

    int wid = tid >> 5, lane = tid & 31;
    int wr = wid >> 2, wc = wid & 3;
    int m0 = wr * 64, n0w = wc * 16;

    float acc[4][2][4];
#pragma unroll
    for (int i = 0; i < 4; ++i)
#pragma unroll
        for (int j = 0; j < 2; ++j)
#pragma unroll
            for (int k = 0; k < 4; ++k) acc[i][j][k] = 0.0f;

#define FISSUE_A(kc, st) do { \
    _Pragma("unroll") \
    for (int i = 0; i < 8; ++i) { \
        int tt = i * 256 + tid; \
        int plane = tt >> 10; \
        int row = (tt >> 3) & 127; \
        int seg = tt & 7; \
        int rg = rbase + row; if (rg > rclamp) rg = rclamp; \
        const __nv_bfloat16* gp = (plane ? aL : aH) + (size_t)rg * Hsz + (kc) * 64 + seg * 8; \
        uint32_t da = sbase + FSM_A_OFF + (st) * 32768 + plane * 16384 + row * 128 + \
                      (((seg ^ (row & 7))) << 4); \
        CP_ASYNC16(da, gp); \
    } } while (0)

#define FISSUE_B(kc) do { \
    _Pragma("unroll") \
    for (int i = 0; i < 4; ++i) { \
        int tt = i * 256 + tid; \
        int plane = tt >> 9; \
        int row = (tt >> 3) & 63; \
        int seg = tt & 7; \
        const __nv_bfloat16* gp = (plane ? Wl : Wh) + (size_t)row * Hsz + (kc) * 64 + seg * 8; \
        uint32_t da = sbase + FSM_B_OFF + plane * 8192 + row * 128 + \
                      (((seg ^ (row & 7))) << 4); \
        CP_ASYNC16(da, gp); \
    } } while (0)

    FISSUE_A(0, 0); FISSUE_B(0);
    CP_COMMIT();
    CP_WAIT0();
    __syncthreads();

    for (int kc = 0; kc < 8; ++kc) {
        int st = kc & 1;
        if (kc < 7) {
            FISSUE_A(kc + 1, st ^ 1);
            CP_COMMIT();
        }
        uint32_t aBase = sbase + FSM_A_OFF + st * 32768;
        uint32_t bBase = sbase + FSM_B_OFF;
#pragma unroll
        for (int j = 0; j < 4; ++j) {
            uint32_t bh[2][2], bl[2][2], af[4][4];
            int kb = (lane >> 4);
            {
                int lrow = n0w + (lane & 15);
                uint32_t addr = bBase + lrow * 128 + (((j * 2 + kb) ^ (lrow & 7)) << 4);
                uint32_t r0, r1, r2, r3;
                LDM4(r0, r1, r2, r3, addr);
                bh[0][0] = r0; bh[0][1] = r2; bh[1][0] = r1; bh[1][1] = r3;
                LDM4(r0, r1, r2, r3, addr + 8192);
                bl[0][0] = r0; bl[0][1] = r2; bl[1][0] = r1; bl[1][1] = r3;
            }
#pragma unroll
            for (int ti = 0; ti < 4; ++ti) {
                int lrow = m0 + ti * 16 + (lane & 15);
                uint32_t addr = aBase + lrow * 128 + (((j * 2 + kb) ^ (lrow & 7)) << 4);
                LDM4(af[ti][0], af[ti][1], af[ti][2], af[ti][3], addr);
            }
#pragma unroll
            for (int mi = 0; mi < 4; ++mi)
#pragma unroll
                for (int nj = 0; nj < 2; ++nj) {
                    MMA16816(acc[mi][nj], af[mi], bh[nj][0], bh[nj][1]);
                    MMA16816(acc[mi][nj], af[mi], bl[nj][0], bl[nj][1]);
                }
#pragma unroll
            for (int ti = 0; ti < 4; ++ti) {
                int lrow = m0 + ti * 16 + (lane & 15);
                uint32_t addr = aBase + 16384 + lrow * 128 + (((j * 2 + kb) ^ (lrow & 7)) << 4);
                LDM4(af[ti][0], af[ti][1], af[ti][2], af[ti][3], addr);
            }
#pragma unroll
            for (int mi = 0; mi < 4; ++mi)
#pragma unroll
                for (int nj = 0; nj < 2; ++nj)
                    MMA16816(acc[mi][nj], af[mi], bh[nj][0], bh[nj][1]);
        }
        __syncthreads();
        if (kc < 7) {
            FISSUE_B(kc + 1);
            CP_COMMIT();
            CP_WAIT0();
            __syncthreads();
        }
    }

#pragma unroll
    for (int mi = 0; mi < 4; ++mi)
#pragma unroll
        for (int half = 0; half < 2; ++half) {
            int r = rbase + m0 + mi * 16 + (lane >> 2) + half * 8;
            if (r < row_hi) {
                int ob = g_perm[r];
#pragma unroll
                for (int nj = 0; nj < 2; ++nj) {
                    int cl = n0w + nj * 8 + (lane & 3) * 2;
                    float2 o;
                    o.x = acc[mi][nj][half * 2 + 0] + sbias[cl];
                    o.y = acc[mi][nj][half * 2 + 1] + sbias[cl + 1];
                    *(float2*)(out + (size_t)ob * Ssz + cl) = o;
                }
            }
        }
#undef FISSUE_A
#undef FISSUE_B
}

// ---------------- launch ----------------
extern "C" void kernel_launch(void* const* d_in, const int* in_sizes, int n_in,
                              void* d_out, int out_size) {
    const float* z   = (const float*)d_in[0];
    const int*   y   = (const int*)d_in[1];
    const float* tW0 = (const float*)d_in[2];
    const float* tb0 = (const float*)d_in[3];
    const float* tW1 = (const float*)d_in[4];
    const float* tb1 = (const float*)d_in[5];
    const float* tW2 = (const float*)d_in[6];
    const float* tb2 = (const float*)d_in[7];
    const float* tW3 = (const float*)d_in[8];
    const float* tb3 = (const float*)d_in[9];
    const float* hW0 = (const float*)d_in[10];
    const float* hb0 = (const float*)d_in[11];
    const float* hW1 = (const float*)d_in[12];
    const float* hb1 = (const float*)d_in[13];
    const float* hW2 = (const float*)d_in[14];
    const float* hb2 = (const float*)d_in[15];
    const float* hW3 = (const float*)d_in[16];
    const float* hb3 = (const float*)d_in[17];
    float* out = (float*)d_out;

    cudaFuncSetAttribute(k_hmma, cudaFuncAttributeMaxDynamicSharedMemorySize, SMEM_MAIN);
    cudaFuncSetAttribute(k_fin, cudaFuncAttributeMaxDynamicSharedMemorySize, SMEM_FIN);

    // launch order fixed so the profiled slot (idx 3) is the first GEMM
    k_bucket<<<1, 1024>>>(y);                                         // 0
    k_prep_all<<<13568, dim3(32, 8)>>>(tW1, tW2, tW3, hW0, hW1, hW2, hW3); // 1
    k_layer0<<<Bsz / 32, 256>>>(z, tW0, tb0);                         // 2

    // trunk: buf0 -> buf1 -> buf0 -> buf1
    k_hmma<<<dim3(4, 64), 256, SMEM_MAIN>>>(0, 1, 0, 0, tb1, 0, 0);   // 3 <- profiled
    k_hmma<<<dim3(4, 64), 256, SMEM_MAIN>>>(1, 0, 0, 1, tb2, 0, 0);
    k_hmma<<<dim3(4, 64), 256, SMEM_MAIN>>>(0, 1, 0, 2, tb3, 0, 0);
    // heads: buf1 -> buf0 -> buf1 -> buf0
    k_hmma<<<dim3(4, 80), 256, SMEM_MAIN>>>(1, 0, 1, 0, hb0, Hsz, 1);
    k_hmma<<<dim3(4, 80), 256, SMEM_MAIN>>>(0, 1, 1, 1, hb1, Hsz, 1);
    k_hmma<<<dim3(4, 80), 256, SMEM_MAIN>>>(1, 0, 1, 2, hb2, Hsz, 1);
    // final: buf0 -> out
    k_fin<<<dim3(1, 80), 256, SMEM_FIN>>>(0, hb3, out);
}

// round 6
// speedup vs baseline: 2.2304x; 1.1470x over previous
#include <cuda_runtime.h>
#include <cuda_bf16.h>
#include <cstdint>

#define Bsz 8192
#define Lsz 16
#define Hsz 512
#define Ssz 64
#define Dsz 16

// ---------------- device scratch ----------------
__device__ int g_perm[Bsz];
__device__ int g_dstart[Dsz + 1];
__device__ int g_tile_d[96];    // 128-row granularity tiles (heads + final)
__device__ int g_tile_r0[96];
__device__ int g_ntiles;

// activations: bf16 hi/lo planes, ping-pong buffers
__device__ __nv_bfloat16 g_aH[2][Bsz * Hsz];
__device__ __nv_bfloat16 g_aL[2][Bsz * Hsz];

// weights: bf16 hi/lo planes, transposed to [N, K] K-major
__device__ __nv_bfloat16 g_tWh[3][Hsz * Hsz];
__device__ __nv_bfloat16 g_tWl[3][Hsz * Hsz];
__device__ __nv_bfloat16 g_hWh[3][Dsz * Hsz * Hsz];
__device__ __nv_bfloat16 g_hWl[3][Dsz * Hsz * Hsz];
__device__ __nv_bfloat16 g_fWh[Dsz * Ssz * Hsz];
__device__ __nv_bfloat16 g_fWl[Dsz * Ssz * Hsz];

__device__ __forceinline__ float lrelu(float x) { return x >= 0.0f ? x : 0.2f * x; }

__device__ __forceinline__ uint32_t smem_u32(const void* p) {
    uint32_t a;
    asm("{ .reg .u64 t; cvta.to.shared.u64 t, %1; cvt.u32.u64 %0, t; }" : "=r"(a) : "l"(p));
    return a;
}

#define CP_ASYNC16(daddr, gp) \
    asm volatile("cp.async.cg.shared.global [%0], [%1], 16;" :: "r"(daddr), "l"(gp))
#define CP_COMMIT() asm volatile("cp.async.commit_group;" ::: "memory")
#define CP_WAIT0() asm volatile("cp.async.wait_group 0;" ::: "memory")

#define LDM4(r0, r1, r2, r3, addr) \
    asm volatile("ldmatrix.sync.aligned.m8n8.x4.shared.b16 {%0,%1,%2,%3}, [%4];" \
                 : "=r"(r0), "=r"(r1), "=r"(r2), "=r"(r3) : "r"(addr))

#define MMA16816(c, a, b0, b1) \
    asm volatile("mma.sync.aligned.m16n8k16.row.col.f32.bf16.bf16.f32 " \
                 "{%0,%1,%2,%3}, {%4,%5,%6,%7}, {%8,%9}, {%0,%1,%2,%3};" \
                 : "+f"((c)[0]), "+f"((c)[1]), "+f"((c)[2]), "+f"((c)[3]) \
                 : "r"((a)[0]), "r"((a)[1]), "r"((a)[2]), "r"((a)[3]), "r"(b0), "r"(b1))

__device__ __forceinline__ uint32_t bfpack(float a, float b) {
    __nv_bfloat16 ha = __float2bfloat16(a), hb = __float2bfloat16(b);
    return (uint32_t)__bfloat16_as_ushort(ha) | ((uint32_t)__bfloat16_as_ushort(hb) << 16);
}

// ---------------- fused bucketing: hist + prefix + scatter + tile list ----------------
__global__ __launch_bounds__(1024) void k_bucket(const int* __restrict__ y) {
    __shared__ int cnt[Dsz];
    __shared__ int off[Dsz];
    int tid = threadIdx.x;
    if (tid < Dsz) cnt[tid] = 0;
    __syncthreads();
    for (int i = tid; i < Bsz; i += 1024) atomicAdd(&cnt[y[i]], 1);
    __syncthreads();
    if (tid == 0) {
        int s = 0;
        int nt = 0;
        for (int d = 0; d < Dsz; ++d) {
            g_dstart[d] = s;
            off[d] = s;
            for (int r = s; r < s + cnt[d]; r += 128) {
                g_tile_d[nt] = d;
                g_tile_r0[nt] = r;
                nt++;
            }
            s += cnt[d];
        }
        g_dstart[Dsz] = s;
        g_ntiles = nt;
    }
    __syncthreads();
    for (int i = tid; i < Bsz; i += 1024) {
        int p = atomicAdd(&off[y[i]], 1);
        g_perm[p] = i;
    }
}

// ---------------- unified weight prep: fp32 [K,N] -> bf16 hi/lo [N,K] ----------------
__global__ void k_prep_all(const float* __restrict__ tW1, const float* __restrict__ tW2,
                           const float* __restrict__ tW3, const float* __restrict__ hW0,
                           const float* __restrict__ hW1, const float* __restrict__ hW2,
                           const float* __restrict__ hW3) {
    __shared__ float t[32][33];
    int gid = blockIdx.x;
    const float* W;
    __nv_bfloat16 *Th, *Tl;
    int N, bx, by;
    if (gid < 768) {
        int l = gid >> 8, rem = gid & 255;
        bx = rem & 15; by = rem >> 4;
        W = (l == 0) ? tW1 : (l == 1) ? tW2 : tW3;
        N = Hsz;
        Th = g_tWh[l]; Tl = g_tWl[l];
    } else if (gid < 13056) {
        int q = gid - 768;
        int l = q / 4096;
        int q2 = q & 4095;
        int z = q2 >> 8, rem = q2 & 255;
        bx = rem & 15; by = rem >> 4;
        const float* base = (l == 0) ? hW0 : (l == 1) ? hW1 : hW2;
        W = base + (size_t)z * Hsz * Hsz;
        N = Hsz;
        size_t o = (size_t)z * Hsz * Hsz;
        Th = g_hWh[l] + o; Tl = g_hWl[l] + o;
    } else {
        int q = gid - 13056;
        int z = q >> 5, rem = q & 31;
        bx = rem & 1; by = rem >> 1;
        W = hW3 + (size_t)z * Hsz * Ssz;
        N = Ssz;
        size_t o = (size_t)z * Ssz * Hsz;
        Th = g_fWh + o; Tl = g_fWl + o;
    }
    int n0 = bx * 32, k0 = by * 32;
    int tx = threadIdx.x, ty = threadIdx.y;
#pragma unroll
    for (int i = 0; i < 4; ++i)
        t[ty + 8 * i][tx] = W[(size_t)(k0 + ty + 8 * i) * N + n0 + tx];
    __syncthreads();
#pragma unroll
    for (int i = 0; i < 4; ++i) {
        float v = t[tx][ty + 8 * i];
        int n = n0 + ty + 8 * i, k = k0 + tx;
        __nv_bfloat16 h = __float2bfloat16(v);
        Th[(size_t)n * Hsz + k] = h;
        Tl[(size_t)n * Hsz + k] = __float2bfloat16(v - __bfloat162float(h));
    }
}

// ---------------- layer 0: lrelu(z[perm] @ tW0 + b) -> split hi/lo into buf 0 ----------
__global__ __launch_bounds__(256) void k_layer0(const float* __restrict__ z,
                                                const float* __restrict__ W,
                                                const float* __restrict__ bias) {
    __shared__ float sW[Lsz * Hsz];
    __shared__ float sb[Hsz];
    int tid = threadIdx.x;
    for (int i = tid; i < Lsz * Hsz; i += 256) sW[i] = W[i];
    for (int i = tid; i < Hsz; i += 256) sb[i] = bias[i];
    __syncthreads();

    int w = tid >> 5, lane = tid & 31;
    for (int q = 0; q < 4; ++q) {
        int p = blockIdx.x * 32 + w * 4 + q;
        int b = g_perm[p];
        float zr[Lsz];
#pragma unroll
        for (int k = 0; k < Lsz; ++k) zr[k] = __ldg(&z[b * Lsz + k]);
#pragma unroll
        for (int it = 0; it < 8; ++it) {
            int c = it * 64 + lane * 2;
            float a0 = sb[c], a1 = sb[c + 1];
#pragma unroll
            for (int k = 0; k < Lsz; ++k) {
                a0 = fmaf(zr[k], sW[k * Hsz + c], a0);
                a1 = fmaf(zr[k], sW[k * Hsz + c + 1], a1);
            }
            a0 = lrelu(a0); a1 = lrelu(a1);
            __nv_bfloat16 h0 = __float2bfloat16(a0), h1 = __float2bfloat16(a1);
            float l0 = a0 - __bfloat162float(h0), l1 = a1 - __bfloat162float(h1);
            size_t o = (size_t)p * Hsz + c;
            *(uint32_t*)(&g_aH[0][o]) = (uint32_t)__bfloat16_as_ushort(h0) |
                                        ((uint32_t)__bfloat16_as_ushort(h1) << 16);
            *(uint32_t*)(&g_aL[0][o]) = bfpack(l0, l1);
        }
    }
}

// ---------------- HMMA GEMM: 128x128 tile, 512 threads, warp tile 32x32, bf16x3 --------
// smem: [0,512) bias; A @1024: [2 st][2 pl][16384] = 65536; B @66560: [2 st][2 pl][16384].
// total 132096 (~129KB) -> 1 CTA/SM, 16 warps resident.
#define SM_A_OFF 1024
#define SM_B_OFF 66560
#define SMEM_MAIN 132096

__global__ __launch_bounds__(512) void k_hmma(int src, int dst, int wsel, int lidx,
                                              const float* __restrict__ bias,
                                              int bStride, int headMode) {
    extern __shared__ char sm[];
    int tid = threadIdx.x;
    int t = blockIdx.y;
    int d, rbase, row_hi;
    if (headMode) {
        if (t >= g_ntiles) return;
        d = g_tile_d[t]; rbase = g_tile_r0[t]; row_hi = g_dstart[d + 1];
    } else {
        d = 0; rbase = t * 128; row_hi = Bsz;
    }
    int cb0 = blockIdx.x * 128;
    int rclamp = row_hi - 1;

    const __nv_bfloat16* aH = g_aH[src];
    const __nv_bfloat16* aL = g_aL[src];
    __nv_bfloat16* oH = g_aH[dst];
    __nv_bfloat16* oL = g_aL[dst];
    const __nv_bfloat16 *Wh, *Wl;
    if (wsel == 0) { Wh = g_tWh[lidx]; Wl = g_tWl[lidx]; }
    else { size_t o = (size_t)d * Hsz * Hsz; Wh = g_hWh[lidx] + o; Wl = g_hWl[lidx] + o; }
    Wh += (size_t)cb0 * Hsz;
    Wl += (size_t)cb0 * Hsz;
    const float* bp = bias + (size_t)d * bStride + cb0;

    float* sbias = (float*)sm;
    if (tid < 128) sbias[tid] = bp[tid];
    uint32_t sbase = smem_u32(sm);

    int wid = tid >> 5, lane = tid & 31;
    int wr = wid >> 2, wc = wid & 3;           // 4 x 4 warp grid
    int m0 = wr * 32, n0w = wc * 32;           // warp tile 32 x 32

    float acc[2][4][4];
#pragma unroll
    for (int i = 0; i < 2; ++i)
#pragma unroll
        for (int j = 0; j < 4; ++j)
#pragma unroll
            for (int k = 0; k < 4; ++k) acc[i][j][k] = 0.0f;

    // A tile copy: 2 planes x 128 rows x 8 segs = 2048 segs, 4/thread @512
#define ISSUE_A(kc, st) do { \
    _Pragma("unroll") \
    for (int i = 0; i < 4; ++i) { \
        int tt = i * 512 + tid; \
        int plane = tt >> 10; \
        int row = (tt >> 3) & 127; \
        int seg = tt & 7; \
        int rg = rbase + row; if (rg > rclamp) rg = rclamp; \
        const __nv_bfloat16* gp = (plane ? aL : aH) + (size_t)rg * Hsz + (kc) * 64 + seg * 8; \
        uint32_t da = sbase + SM_A_OFF + (st) * 32768 + plane * 16384 + row * 128 + \
                      (((seg ^ (row & 7))) << 4); \
        CP_ASYNC16(da, gp); \
    } } while (0)

#define ISSUE_B(kc, st) do { \
    _Pragma("unroll") \
    for (int i = 0; i < 4; ++i) { \
        int tt = i * 512 + tid; \
        int plane = tt >> 10; \
        int row = (tt >> 3) & 127; \
        int seg = tt & 7; \
        const __nv_bfloat16* gp = (plane ? Wl : Wh) + (size_t)row * Hsz + (kc) * 64 + seg * 8; \
        uint32_t da = sbase + SM_B_OFF + (st) * 32768 + plane * 16384 + row * 128 + \
                      (((seg ^ (row & 7))) << 4); \
        CP_ASYNC16(da, gp); \
    } } while (0)

    ISSUE_A(0, 0); ISSUE_B(0, 0);
    CP_COMMIT();
    CP_WAIT0();
    __syncthreads();

    for (int kc = 0; kc < 8; ++kc) {
        int st = kc & 1;
        if (kc < 7) {
            ISSUE_A(kc + 1, st ^ 1);
            ISSUE_B(kc + 1, st ^ 1);
            CP_COMMIT();
        }
        uint32_t aBase = sbase + SM_A_OFF + st * 32768;
        uint32_t bBase = sbase + SM_B_OFF + st * 32768;
#pragma unroll
        for (int j = 0; j < 4; ++j) {
            uint32_t bh[4][2], bl[4][2], af[2][4];
            int kb = (lane >> 4);
#pragma unroll
            for (int nt = 0; nt < 2; ++nt) {
                int lrow = n0w + nt * 16 + (lane & 15);
                uint32_t addr = bBase + lrow * 128 + (((j * 2 + kb) ^ (lrow & 7)) << 4);
                uint32_t r0, r1, r2, r3;
                LDM4(r0, r1, r2, r3, addr);
                bh[nt * 2][0] = r0; bh[nt * 2][1] = r2;
                bh[nt * 2 + 1][0] = r1; bh[nt * 2 + 1][1] = r3;
                LDM4(r0, r1, r2, r3, addr + 16384);
                bl[nt * 2][0] = r0; bl[nt * 2][1] = r2;
                bl[nt * 2 + 1][0] = r1; bl[nt * 2 + 1][1] = r3;
            }
            // A hi-plane frags: Ah*Bh + Ah*Bl
#pragma unroll
            for (int ti = 0; ti < 2; ++ti) {
                int lrow = m0 + ti * 16 + (lane & 15);
                uint32_t addr = aBase + lrow * 128 + (((j * 2 + kb) ^ (lrow & 7)) << 4);
                LDM4(af[ti][0], af[ti][1], af[ti][2], af[ti][3], addr);
            }
#pragma unroll
            for (int mi = 0; mi < 2; ++mi)
#pragma unroll
                for (int nj = 0; nj < 4; ++nj) {
                    MMA16816(acc[mi][nj], af[mi], bh[nj][0], bh[nj][1]);
                    MMA16816(acc[mi][nj], af[mi], bl[nj][0], bl[nj][1]);
                }
            // A lo-plane frags (reuse af): Al*Bh
#pragma unroll
            for (int ti = 0; ti < 2; ++ti) {
                int lrow = m0 + ti * 16 + (lane & 15);
                uint32_t addr = aBase + 16384 + lrow * 128 + (((j * 2 + kb) ^ (lrow & 7)) << 4);
                LDM4(af[ti][0], af[ti][1], af[ti][2], af[ti][3], addr);
            }
#pragma unroll
            for (int mi = 0; mi < 2; ++mi)
#pragma unroll
                for (int nj = 0; nj < 4; ++nj)
                    MMA16816(acc[mi][nj], af[mi], bh[nj][0], bh[nj][1]);
        }
        if (kc < 7) CP_WAIT0();
        __syncthreads();
    }

    // epilogue: bias + lrelu, split to hi/lo bf16, store
#pragma unroll
    for (int mi = 0; mi < 2; ++mi)
#pragma unroll
        for (int half = 0; half < 2; ++half) {
            int r = rbase + m0 + mi * 16 + (lane >> 2) + half * 8;
            if (r < row_hi) {
#pragma unroll
                for (int nj = 0; nj < 4; ++nj) {
                    int cl = n0w + nj * 8 + (lane & 3) * 2;
                    float v0 = lrelu(acc[mi][nj][half * 2 + 0] + sbias[cl]);
                    float v1 = lrelu(acc[mi][nj][half * 2 + 1] + sbias[cl + 1]);
                    __nv_bfloat16 h0 = __float2bfloat16(v0), h1 = __float2bfloat16(v1);
                    float l0 = v0 - __bfloat162float(h0), l1 = v1 - __bfloat162float(h1);
                    size_t o = (size_t)r * Hsz + cb0 + cl;
                    *(uint32_t*)(&oH[o]) = (uint32_t)__bfloat16_as_ushort(h0) |
                                           ((uint32_t)__bfloat16_as_ushort(h1) << 16);
                    *(uint32_t*)(&oL[o]) = bfpack(l0, l1);
                }
            }
        }
#undef ISSUE_A
#undef ISSUE_B
}

// ---------------- final layer: 128x64 tile, 256 threads, scatter to out[perm] ----------
// smem: [0,256) bias; A @1024: [2][2][16384]; B @66560: [2][8192]. total 82944.
#define FSM_A_OFF 1024
#define FSM_B_OFF 66560
#define SMEM_FIN 82944

__global__ __launch_bounds__(256) void k_fin(int src, const float* __restrict__ bias,
                                             float* __restrict__ out) {
    extern __shared__ char sm[];
    int tid = threadIdx.x;
    int t = blockIdx.y;
    if (t >= g_ntiles) return;
    int d = g_tile_d[t];
    int rbase = g_tile_r0[t];
    int row_hi = g_dstart[d + 1];
    int rclamp = row_hi - 1;

    const __nv_bfloat16* aH = g_aH[src];
    const __nv_bfloat16* aL = g_aL[src];
    const __nv_bfloat16* Wh = g_fWh + (size_t)d * Ssz * Hsz;
    const __nv_bfloat16* Wl = g_fWl + (size_t)d * Ssz * Hsz;
    const float* bp = bias + (size_t)d * Ssz;

    float* sbias = (float*)sm;
    if (tid < 64) sbias[tid] = bp[tid];
    uint32_t sbase = smem_u32(sm);

    int wid = tid >> 5, lane = tid & 31;
    int wr = wid >> 2, wc = wid & 3;
    int m0 = wr * 64, n0w = wc * 16;

    float acc[4][2][4];
#pragma unroll
    for (int i = 0; i < 4; ++i)
#pragma unroll
        for (int j = 0; j < 2; ++j)
#pragma unroll
            for (int k = 0; k < 4; ++k) acc[i][j][k] = 0.0f;

#define FISSUE_A(kc, st) do { \
    _Pragma("unroll") \
    for (int i = 0; i < 8; ++i) { \
        int tt = i * 256 + tid; \
        int plane = tt >> 10; \
        int row = (tt >> 3) & 127; \
        int seg = tt & 7; \
        int rg = rbase + row; if (rg > rclamp) rg = rclamp; \
        const __nv_bfloat16* gp = (plane ? aL : aH) + (size_t)rg * Hsz + (kc) * 64 + seg * 8; \
        uint32_t da = sbase + FSM_A_OFF + (st) * 32768 + plane * 16384 + row * 128 + \
                      (((seg ^ (row & 7))) << 4); \
        CP_ASYNC16(da, gp); \
    } } while (0)

#define FISSUE_B(kc) do { \
    _Pragma("unroll") \
    for (int i = 0; i < 4; ++i) { \
        int tt = i * 256 + tid; \
        int plane = tt >> 9; \
        int row = (tt >> 3) & 63; \
        int seg = tt & 7; \
        const __nv_bfloat16* gp = (plane ? Wl : Wh) + (size_t)row * Hsz + (kc) * 64 + seg * 8; \
        uint32_t da = sbase + FSM_B_OFF + plane * 8192 + row * 128 + \
                      (((seg ^ (row & 7))) << 4); \
        CP_ASYNC16(da, gp); \
    } } while (0)

    FISSUE_A(0, 0); FISSUE_B(0);
    CP_COMMIT();
    CP_WAIT0();
    __syncthreads();

    for (int kc = 0; kc < 8; ++kc) {
        int st = kc & 1;
        if (kc < 7) {
            FISSUE_A(kc + 1, st ^ 1);
            CP_COMMIT();
        }
        uint32_t aBase = sbase + FSM_A_OFF + st * 32768;
        uint32_t bBase = sbase + FSM_B_OFF;
#pragma unroll
        for (int j = 0; j < 4; ++j) {
            uint32_t bh[2][2], bl[2][2], af[4][4];
            int kb = (lane >> 4);
            {
                int lrow = n0w + (lane & 15);
                uint32_t addr = bBase + lrow * 128 + (((j * 2 + kb) ^ (lrow & 7)) << 4);
                uint32_t r0, r1, r2, r3;
                LDM4(r0, r1, r2, r3, addr);
                bh[0][0] = r0; bh[0][1] = r2; bh[1][0] = r1; bh[1][1] = r3;
                LDM4(r0, r1, r2, r3, addr + 8192);
                bl[0][0] = r0; bl[0][1] = r2; bl[1][0] = r1; bl[1][1] = r3;
            }
#pragma unroll
            for (int ti = 0; ti < 4; ++ti) {
                int lrow = m0 + ti * 16 + (lane & 15);
                uint32_t addr = aBase + lrow * 128 + (((j * 2 + kb) ^ (lrow & 7)) << 4);
                LDM4(af[ti][0], af[ti][1], af[ti][2], af[ti][3], addr);
            }
#pragma unroll
            for (int mi = 0; mi < 4; ++mi)
#pragma unroll
                for (int nj = 0; nj < 2; ++nj) {
                    MMA16816(acc[mi][nj], af[mi], bh[nj][0], bh[nj][1]);
                    MMA16816(acc[mi][nj], af[mi], bl[nj][0], bl[nj][1]);
                }
#pragma unroll
            for (int ti = 0; ti < 4; ++ti) {
                int lrow = m0 + ti * 16 + (lane & 15);
                uint32_t addr = aBase + 16384 + lrow * 128 + (((j * 2 + kb) ^ (lrow & 7)) << 4);
                LDM4(af[ti][0], af[ti][1], af[ti][2], af[ti][3], addr);
            }
#pragma unroll
            for (int mi = 0; mi < 4; ++mi)
#pragma unroll
                for (int nj = 0; nj < 2; ++nj)
                    MMA16816(acc[mi][nj], af[mi], bh[nj][0], bh[nj][1]);
        }
        __syncthreads();
        if (kc < 7) {
            FISSUE_B(kc + 1);
            CP_COMMIT();
            CP_WAIT0();
            __syncthreads();
        }
    }

#pragma unroll
    for (int mi = 0; mi < 4; ++mi)
#pragma unroll
        for (int half = 0; half < 2; ++half) {
            int r = rbase + m0 + mi * 16 + (lane >> 2) + half * 8;
            if (r < row_hi) {
                int ob = g_perm[r];
#pragma unroll
                for (int nj = 0; nj < 2; ++nj) {
                    int cl = n0w + nj * 8 + (lane & 3) * 2;
                    float2 o;
                    o.x = acc[mi][nj][half * 2 + 0] + sbias[cl];
                    o.y = acc[mi][nj][half * 2 + 1] + sbias[cl + 1];
                    *(float2*)(out + (size_t)ob * Ssz + cl) = o;
                }
            }
        }
#undef FISSUE_A
#undef FISSUE_B
}

// ---------------- launch ----------------
extern "C" void kernel_launch(void* const* d_in, const int* in_sizes, int n_in,
                              void* d_out, int out_size) {
    const float* z   = (const float*)d_in[0];
    const int*   y   = (const int*)d_in[1];
    const float* tW0 = (const float*)d_in[2];
    const float* tb0 = (const float*)d_in[3];
    const float* tW1 = (const float*)d_in[4];
    const float* tb1 = (const float*)d_in[5];
    const float* tW2 = (const float*)d_in[6];
    const float* tb2 = (const float*)d_in[7];
    const float* tW3 = (const float*)d_in[8];
    const float* tb3 = (const float*)d_in[9];
    const float* hW0 = (const float*)d_in[10];
    const float* hb0 = (const float*)d_in[11];
    const float* hW1 = (const float*)d_in[12];
    const float* hb1 = (const float*)d_in[13];
    const float* hW2 = (const float*)d_in[14];
    const float* hb2 = (const float*)d_in[15];
    const float* hW3 = (const float*)d_in[16];
    const float* hb3 = (const float*)d_in[17];
    float* out = (float*)d_out;

    cudaFuncSetAttribute(k_hmma, cudaFuncAttributeMaxDynamicSharedMemorySize, SMEM_MAIN);
    cudaFuncSetAttribute(k_fin, cudaFuncAttributeMaxDynamicSharedMemorySize, SMEM_FIN);

    k_bucket<<<1, 1024>>>(y);                                         // 0
    k_prep_all<<<13568, dim3(32, 8)>>>(tW1, tW2, tW3, hW0, hW1, hW2, hW3); // 1
    k_layer0<<<Bsz / 32, 256>>>(z, tW0, tb0);                         // 2

    // trunk: buf0 -> buf1 -> buf0 -> buf1
    k_hmma<<<dim3(4, 64), 512, SMEM_MAIN>>>(0, 1, 0, 0, tb1, 0, 0);   // 3 <- profiled
    k_hmma<<<dim3(4, 64), 512, SMEM_MAIN>>>(1, 0, 0, 1, tb2, 0, 0);
    k_hmma<<<dim3(4, 64), 512, SMEM_MAIN>>>(0, 1, 0, 2, tb3, 0, 0);
    // heads: buf1 -> buf0 -> buf1 -> buf0
    k_hmma<<<dim3(4, 80), 512, SMEM_MAIN>>>(1, 0, 1, 0, hb0, Hsz, 1);
    k_hmma<<<dim3(4, 80), 512, SMEM_MAIN>>>(0, 1, 1, 1, hb1, Hsz, 1);
    k_hmma<<<dim3(4, 80), 512, SMEM_MAIN>>>(1, 0, 1, 2, hb2, Hsz, 1);
    // final: buf0 -> out
    k_fin<<<dim3(1, 80), 256, SMEM_FIN>>>(0, hb3, out);
}